// round 7
// baseline (speedup 1.0000x reference)
#include <cuda_runtime.h>
#include <cuda_bf16.h>

#define N_NODES 100000
#define N_EDGES 1600000
#define SCAN_B  512
#define SCAN_NBLK ((N_NODES + SCAN_B - 1) / SCAN_B)   // 196

// ---------------- scratch (device globals; referenced ONLY in device code) ---
__device__ int   g_is64;                  // 1 if edge_index really is int64
__device__ int   g_src   [N_EDGES];
__device__ int   g_dst   [N_EDGES];
__device__ int   g_hist  [N_NODES];
__device__ int   g_off   [N_NODES + 1];
__device__ int   g_cursor[N_NODES];
__device__ int   g_blocksum[SCAN_NBLK + 1];
__device__ int   g_srcs  [N_EDGES];       // CSR adjacency (source per slot)
__device__ float g_mean1 [N_NODES * 64];
__device__ float g_h     [N_NODES * 128];
__device__ float g_hw    [N_NODES * 64];  // h @ W2_l
__device__ float g_mean2 [N_NODES * 64];  // mean of hw over neighbors

// ---------------- dtype detection + conversion -------------------------------
// If the buffer holds int64 node ids (< 2^32 each), every 8-byte word has a
// zero high half. If it holds int32 pairs, high halves are ~uniform indices.
__global__ void detect_kernel(const void* __restrict__ ei_raw) {
    if (threadIdx.x == 0 && blockIdx.x == 0) {
        const unsigned long long* p = (const unsigned long long*)ei_raw;
        int is64 = 1;
        for (int i = 0; i < 64; i++)
            if (p[i] >= (1ULL << 32)) { is64 = 0; break; }
        g_is64 = is64;
    }
}

__device__ __forceinline__ int clamp_idx(long long v) {
    if (v < 0) return 0;
    if (v >= N_NODES) return N_NODES - 1;
    return (int)v;
}

__global__ __launch_bounds__(256) void convert_kernel(const void* __restrict__ ei_raw) {
    int e = blockIdx.x * blockDim.x + threadIdx.x;
    if (e >= N_EDGES) return;
    if (g_is64) {
        const long long* p = (const long long*)ei_raw;
        g_src[e] = clamp_idx(p[e]);
        g_dst[e] = clamp_idx(p[N_EDGES + e]);
    } else {
        const int* p = (const int*)ei_raw;
        g_src[e] = clamp_idx((long long)p[e]);
        g_dst[e] = clamp_idx((long long)p[N_EDGES + e]);
    }
}

// ---------------- CSR build --------------------------------------------------
__global__ void zero_hist_kernel() {
    int i = blockIdx.x * blockDim.x + threadIdx.x;
    if (i < N_NODES) g_hist[i] = 0;
}

__global__ __launch_bounds__(256) void hist_kernel() {
    int e = blockIdx.x * blockDim.x + threadIdx.x;
    if (e >= N_EDGES) return;
    atomicAdd(&g_hist[g_dst[e]], 1);
}

__global__ __launch_bounds__(SCAN_B) void scan_blocksums_kernel() {
    __shared__ int sh[SCAN_B];
    int i = blockIdx.x * SCAN_B + threadIdx.x;
    sh[threadIdx.x] = (i < N_NODES) ? g_hist[i] : 0;
    __syncthreads();
    for (int s = SCAN_B / 2; s > 0; s >>= 1) {
        if (threadIdx.x < s) sh[threadIdx.x] += sh[threadIdx.x + s];
        __syncthreads();
    }
    if (threadIdx.x == 0) g_blocksum[blockIdx.x] = sh[0];
}

__global__ void scan_blockoffsets_kernel() {
    if (threadIdx.x == 0 && blockIdx.x == 0) {
        int run = 0;
        for (int i = 0; i < SCAN_NBLK; i++) {
            int t = g_blocksum[i];
            g_blocksum[i] = run;
            run += t;
        }
        g_blocksum[SCAN_NBLK] = run;
    }
}

__global__ __launch_bounds__(SCAN_B) void scan_offsets_kernel() {
    __shared__ int sh[SCAN_B];
    int i = blockIdx.x * SCAN_B + threadIdx.x;
    int v = (i < N_NODES) ? g_hist[i] : 0;
    sh[threadIdx.x] = v;
    __syncthreads();
    for (int s = 1; s < SCAN_B; s <<= 1) {
        int t = (threadIdx.x >= s) ? sh[threadIdx.x - s] : 0;
        __syncthreads();
        sh[threadIdx.x] += t;
        __syncthreads();
    }
    int excl = g_blocksum[blockIdx.x] + sh[threadIdx.x] - v;
    if (i < N_NODES) {
        g_off[i] = excl;
        g_cursor[i] = excl;
        if (i == N_NODES - 1) g_off[N_NODES] = excl + v;
    }
}

__global__ __launch_bounds__(256) void fill_kernel() {
    int e = blockIdx.x * blockDim.x + threadIdx.x;
    if (e >= N_EDGES) return;
    int pos = atomicAdd(&g_cursor[g_dst[e]], 1);
    g_srcs[pos] = g_src[e];
}

// ---------------- gather-mean aggregation, layer 1 (x -> g_mean1) ------------
// 16 threads per node, each owns one float4 of the 64-wide row.
__global__ __launch_bounds__(256) void agg1_kernel(const float* __restrict__ x)
{
    int t = blockIdx.x * blockDim.x + threadIdx.x;
    int n = t >> 4;
    if (n >= N_NODES) return;
    int p4 = (t & 15) * 4;

    int beg = g_off[n], end = g_off[n + 1];
    float4 acc0 = make_float4(0.f, 0.f, 0.f, 0.f);
    float4 acc1 = make_float4(0.f, 0.f, 0.f, 0.f);

    int i = beg;
    for (; i + 1 < end; i += 2) {
        int s0 = g_srcs[i];
        int s1 = g_srcs[i + 1];
        float4 v0 = *(const float4*)&x[s0 * 64 + p4];
        float4 v1 = *(const float4*)&x[s1 * 64 + p4];
        acc0.x += v0.x; acc0.y += v0.y; acc0.z += v0.z; acc0.w += v0.w;
        acc1.x += v1.x; acc1.y += v1.y; acc1.z += v1.z; acc1.w += v1.w;
    }
    if (i < end) {
        int s0 = g_srcs[i];
        float4 v0 = *(const float4*)&x[s0 * 64 + p4];
        acc0.x += v0.x; acc0.y += v0.y; acc0.z += v0.z; acc0.w += v0.w;
    }

    float inv = 1.f / fmaxf((float)(end - beg), 1.f);
    float4 o;
    o.x = (acc0.x + acc1.x) * inv;
    o.y = (acc0.y + acc1.y) * inv;
    o.z = (acc0.z + acc1.z) * inv;
    o.w = (acc0.w + acc1.w) * inv;
    *(float4*)&g_mean1[n * 64 + p4] = o;
}

// ---------------- gather-mean aggregation, layer 2 (g_hw -> g_mean2) ---------
__global__ __launch_bounds__(256) void agg2_kernel()
{
    int t = blockIdx.x * blockDim.x + threadIdx.x;
    int n = t >> 4;
    if (n >= N_NODES) return;
    int p4 = (t & 15) * 4;

    int beg = g_off[n], end = g_off[n + 1];
    float4 acc0 = make_float4(0.f, 0.f, 0.f, 0.f);
    float4 acc1 = make_float4(0.f, 0.f, 0.f, 0.f);

    int i = beg;
    for (; i + 1 < end; i += 2) {
        int s0 = g_srcs[i];
        int s1 = g_srcs[i + 1];
        float4 v0 = *(const float4*)&g_hw[s0 * 64 + p4];
        float4 v1 = *(const float4*)&g_hw[s1 * 64 + p4];
        acc0.x += v0.x; acc0.y += v0.y; acc0.z += v0.z; acc0.w += v0.w;
        acc1.x += v1.x; acc1.y += v1.y; acc1.z += v1.z; acc1.w += v1.w;
    }
    if (i < end) {
        int s0 = g_srcs[i];
        float4 v0 = *(const float4*)&g_hw[s0 * 64 + p4];
        acc0.x += v0.x; acc0.y += v0.y; acc0.z += v0.z; acc0.w += v0.w;
    }

    float inv = 1.f / fmaxf((float)(end - beg), 1.f);
    float4 o;
    o.x = (acc0.x + acc1.x) * inv;
    o.y = (acc0.y + acc1.y) * inv;
    o.z = (acc0.z + acc1.z) * inv;
    o.w = (acc0.w + acc1.w) * inv;
    *(float4*)&g_mean2[n * 64 + p4] = o;
}

// ---------------- dense layer 1: h = relu(mean1 @ W1_l + x @ W1_r + b1) -----
// K=64 in, 128 out. 32-node tile per CTA, 256 threads.
__global__ __launch_bounds__(256) void dense1_kernel(
    const float* __restrict__ x,
    const float* __restrict__ Wl,
    const float* __restrict__ Wr,
    const float* __restrict__ b)
{
    extern __shared__ float sh[];
    float* sWl = sh;                 // 64*128
    float* sWr = sWl + 64 * 128;     // 64*128
    float* sB  = sWr + 64 * 128;     // 128
    float* sM  = sB + 128;           // 32*64
    float* sX  = sM + 32 * 64;       // 32*64

    const int tid = threadIdx.x;
    for (int i = tid; i < 64 * 128; i += 256) { sWl[i] = Wl[i]; sWr[i] = Wr[i]; }
    if (tid < 128) sB[tid] = b[tid];

    const int node0 = blockIdx.x * 32;
    for (int i = tid; i < 32 * 64; i += 256) {
        int ln = i >> 6, f = i & 63;
        int n = node0 + ln;
        if (n < N_NODES) {
            sM[i] = g_mean1[n * 64 + f];
            sX[i] = x[n * 64 + f];
        } else { sM[i] = 0.f; sX[i] = 0.f; }
    }
    __syncthreads();

    const int c4 = (tid & 31) * 4;
    const int ng = tid >> 5;            // 0..7 -> 4 nodes each
    float acc[4][4];
    #pragma unroll
    for (int i = 0; i < 4; i++)
        #pragma unroll
        for (int j = 0; j < 4; j++) acc[i][j] = 0.f;

    #pragma unroll
    for (int k = 0; k < 64; k += 4) {
        float4 mv[4], xv[4];
        #pragma unroll
        for (int i = 0; i < 4; i++) {
            int ln = ng * 4 + i;
            mv[i] = *(const float4*)&sM[ln * 64 + k];
            xv[i] = *(const float4*)&sX[ln * 64 + k];
        }
        #pragma unroll
        for (int kk = 0; kk < 4; kk++) {
            float4 wl = *(const float4*)&sWl[(k + kk) * 128 + c4];
            float4 wr = *(const float4*)&sWr[(k + kk) * 128 + c4];
            #pragma unroll
            for (int i = 0; i < 4; i++) {
                float m  = (&mv[i].x)[kk];
                float xx = (&xv[i].x)[kk];
                acc[i][0] += wl.x * m + wr.x * xx;
                acc[i][1] += wl.y * m + wr.y * xx;
                acc[i][2] += wl.z * m + wr.z * xx;
                acc[i][3] += wl.w * m + wr.w * xx;
            }
        }
    }

    #pragma unroll
    for (int i = 0; i < 4; i++) {
        int n = node0 + ng * 4 + i;
        if (n < N_NODES) {
            float4 o;
            o.x = fmaxf(acc[i][0] + sB[c4 + 0], 0.f);
            o.y = fmaxf(acc[i][1] + sB[c4 + 1], 0.f);
            o.z = fmaxf(acc[i][2] + sB[c4 + 2], 0.f);
            o.w = fmaxf(acc[i][3] + sB[c4 + 3], 0.f);
            *(float4*)&g_h[n * 128 + c4] = o;
        }
    }
}

// ---------------- project: hw = h @ W2_l (K=128 -> 64) -----------------------
__global__ __launch_bounds__(256) void hw_kernel(const float* __restrict__ Wl)
{
    extern __shared__ float sh[];
    float* sW = sh;                  // 128*64
    float* sH = sW + 128 * 64;       // 32*128

    const int tid = threadIdx.x;
    for (int i = tid; i < 128 * 64; i += 256) sW[i] = Wl[i];

    const int node0 = blockIdx.x * 32;
    for (int i = tid; i < 32 * 128; i += 256) {
        int ln = i >> 7, f = i & 127;
        int n = node0 + ln;
        sH[i] = (n < N_NODES) ? g_h[n * 128 + f] : 0.f;
    }
    __syncthreads();

    const int c4 = (tid & 15) * 4;
    const int ng = tid >> 4;            // 0..15 -> 2 nodes each
    float acc[2][4];
    #pragma unroll
    for (int i = 0; i < 2; i++)
        #pragma unroll
        for (int j = 0; j < 4; j++) acc[i][j] = 0.f;

    #pragma unroll 8
    for (int k = 0; k < 128; k += 4) {
        float4 hv[2];
        #pragma unroll
        for (int i = 0; i < 2; i++)
            hv[i] = *(const float4*)&sH[(ng * 2 + i) * 128 + k];
        #pragma unroll
        for (int kk = 0; kk < 4; kk++) {
            float4 w = *(const float4*)&sW[(k + kk) * 64 + c4];
            #pragma unroll
            for (int i = 0; i < 2; i++) {
                float hh = (&hv[i].x)[kk];
                acc[i][0] += w.x * hh;
                acc[i][1] += w.y * hh;
                acc[i][2] += w.z * hh;
                acc[i][3] += w.w * hh;
            }
        }
    }

    #pragma unroll
    for (int i = 0; i < 2; i++) {
        int n = node0 + ng * 2 + i;
        if (n < N_NODES) {
            float4 o = make_float4(acc[i][0], acc[i][1], acc[i][2], acc[i][3]);
            *(float4*)&g_hw[n * 64 + c4] = o;
        }
    }
}

// ---------------- final: out = mean2 + h @ W2_r + b2 -------------------------
__global__ __launch_bounds__(256) void dense2_kernel(
    const float* __restrict__ Wr,
    const float* __restrict__ b,
    float* __restrict__ out)
{
    extern __shared__ float sh[];
    float* sW = sh;                  // 128*64
    float* sH = sW + 128 * 64;       // 32*128
    float* sB = sH + 32 * 128;       // 64

    const int tid = threadIdx.x;
    for (int i = tid; i < 128 * 64; i += 256) sW[i] = Wr[i];
    if (tid < 64) sB[tid] = b[tid];

    const int node0 = blockIdx.x * 32;
    for (int i = tid; i < 32 * 128; i += 256) {
        int ln = i >> 7, f = i & 127;
        int n = node0 + ln;
        sH[i] = (n < N_NODES) ? g_h[n * 128 + f] : 0.f;
    }
    __syncthreads();

    const int c4 = (tid & 15) * 4;
    const int ng = tid >> 4;
    float acc[2][4];
    #pragma unroll
    for (int i = 0; i < 2; i++)
        #pragma unroll
        for (int j = 0; j < 4; j++) acc[i][j] = 0.f;

    #pragma unroll 8
    for (int k = 0; k < 128; k += 4) {
        float4 hv[2];
        #pragma unroll
        for (int i = 0; i < 2; i++)
            hv[i] = *(const float4*)&sH[(ng * 2 + i) * 128 + k];
        #pragma unroll
        for (int kk = 0; kk < 4; kk++) {
            float4 w = *(const float4*)&sW[(k + kk) * 64 + c4];
            #pragma unroll
            for (int i = 0; i < 2; i++) {
                float hh = (&hv[i].x)[kk];
                acc[i][0] += w.x * hh;
                acc[i][1] += w.y * hh;
                acc[i][2] += w.z * hh;
                acc[i][3] += w.w * hh;
            }
        }
    }

    #pragma unroll
    for (int i = 0; i < 2; i++) {
        int n = node0 + ng * 2 + i;
        if (n < N_NODES) {
            float4 m = *(const float4*)&g_mean2[n * 64 + c4];
            float4 o;
            o.x = acc[i][0] + m.x + sB[c4 + 0];
            o.y = acc[i][1] + m.y + sB[c4 + 1];
            o.z = acc[i][2] + m.z + sB[c4 + 2];
            o.w = acc[i][3] + m.w + sB[c4 + 3];
            *(float4*)&out[n * 64 + c4] = o;
        }
    }
}

// ---------------- launch ----------------------------------------------------
extern "C" void kernel_launch(void* const* d_in, const int* in_sizes, int n_in,
                              void* d_out, int out_size)
{
    const float* x   = (const float*)d_in[0];
    const void*  ei  = d_in[1];                 // int32 or int64 — detected on device
    const float* W1l = (const float*)d_in[2];
    const float* W1r = (const float*)d_in[3];
    const float* b1  = (const float*)d_in[4];
    const float* W2l = (const float*)d_in[5];
    const float* W2r = (const float*)d_in[6];
    const float* b2  = (const float*)d_in[7];
    float* out = (float*)d_out;

    const int d1_smem = (64 * 128 * 2 + 128 + 32 * 64 * 2) * (int)sizeof(float);
    const int hw_smem = (128 * 64 + 32 * 128) * (int)sizeof(float);
    const int d2_smem = (128 * 64 + 32 * 128 + 64) * (int)sizeof(float);
    cudaFuncSetAttribute(dense1_kernel, cudaFuncAttributeMaxDynamicSharedMemorySize, d1_smem);
    cudaFuncSetAttribute(hw_kernel,     cudaFuncAttributeMaxDynamicSharedMemorySize, hw_smem);
    cudaFuncSetAttribute(dense2_kernel, cudaFuncAttributeMaxDynamicSharedMemorySize, d2_smem);

    // --- edge-index dtype detection + conversion ---
    detect_kernel<<<1, 32>>>(ei);
    convert_kernel<<<(N_EDGES + 255) / 256, 256>>>(ei);

    // --- CSR build ---
    zero_hist_kernel<<<(N_NODES + 1023) / 1024, 1024>>>();
    hist_kernel<<<(N_EDGES + 255) / 256, 256>>>();
    scan_blocksums_kernel<<<SCAN_NBLK, SCAN_B>>>();
    scan_blockoffsets_kernel<<<1, 32>>>();
    scan_offsets_kernel<<<SCAN_NBLK, SCAN_B>>>();
    fill_kernel<<<(N_EDGES + 255) / 256, 256>>>();

    // --- layer 1 ---
    agg1_kernel<<<(N_NODES * 16 + 255) / 256, 256>>>(x);
    dense1_kernel<<<(N_NODES + 31) / 32, 256, d1_smem>>>(x, W1l, W1r, b1);

    // --- layer 2 (project h first, then aggregate 64-wide) ---
    hw_kernel<<<(N_NODES + 31) / 32, 256, hw_smem>>>(W2l);
    agg2_kernel<<<(N_NODES * 16 + 255) / 256, 256>>>();
    dense2_kernel<<<(N_NODES + 31) / 32, 256, d2_smem>>>(W2r, b2, out);
}

// round 11
// speedup vs baseline: 1.1037x; 1.1037x over previous
#include <cuda_runtime.h>
#include <cuda_bf16.h>

#define N_NODES 100000
#define N_EDGES 1600000
#define SCAN_B  512
#define SCAN_NBLK ((N_NODES + SCAN_B - 1) / SCAN_B)   // 196

// ---------------- scratch (device globals; referenced ONLY in device code) ---
__device__ int   g_is64;
__device__ int   g_src   [N_EDGES];
__device__ int   g_dst   [N_EDGES];
__device__ int   g_hist  [N_NODES];
__device__ int   g_off   [N_NODES + 1];
__device__ int   g_cursor[N_NODES];
__device__ int   g_blocksum[SCAN_NBLK + 1];
__device__ int   g_srcs  [N_EDGES];       // CSR adjacency (source per slot)
__device__ float g_mean1 [N_NODES * 64];
__device__ float g_h     [N_NODES * 128];
__device__ float g_hw    [N_NODES * 64];  // h @ W2_l
__device__ float g_mean2 [N_NODES * 64];  // mean of hw over neighbors

// ---------------- dtype detection -------------------------------------------
__global__ void detect_kernel(const void* __restrict__ ei_raw) {
    if (threadIdx.x == 0 && blockIdx.x == 0) {
        const unsigned long long* p = (const unsigned long long*)ei_raw;
        int is64 = 1;
        for (int i = 0; i < 64; i++)
            if (p[i] >= (1ULL << 32)) { is64 = 0; break; }
        g_is64 = is64;
    }
}

__device__ __forceinline__ int clamp_idx(long long v) {
    if (v < 0) return 0;
    if (v >= N_NODES) return N_NODES - 1;
    return (int)v;
}

__global__ void zero_hist_kernel() {
    int i = blockIdx.x * blockDim.x + threadIdx.x;
    if (i < N_NODES) g_hist[i] = 0;
}

// fused convert + degree histogram (single pass over edge list)
__global__ __launch_bounds__(256) void convert_hist_kernel(const void* __restrict__ ei_raw) {
    int e = blockIdx.x * blockDim.x + threadIdx.x;
    if (e >= N_EDGES) return;
    int s, d;
    if (g_is64) {
        const long long* p = (const long long*)ei_raw;
        s = clamp_idx(p[e]);
        d = clamp_idx(p[N_EDGES + e]);
    } else {
        const int* p = (const int*)ei_raw;
        s = clamp_idx((long long)p[e]);
        d = clamp_idx((long long)p[N_EDGES + e]);
    }
    g_src[e] = s;
    g_dst[e] = d;
    atomicAdd(&g_hist[d], 1);
}

// ---------------- CSR scan + fill -------------------------------------------
__global__ __launch_bounds__(SCAN_B) void scan_blocksums_kernel() {
    __shared__ int sh[SCAN_B];
    int i = blockIdx.x * SCAN_B + threadIdx.x;
    sh[threadIdx.x] = (i < N_NODES) ? g_hist[i] : 0;
    __syncthreads();
    for (int s = SCAN_B / 2; s > 0; s >>= 1) {
        if (threadIdx.x < s) sh[threadIdx.x] += sh[threadIdx.x + s];
        __syncthreads();
    }
    if (threadIdx.x == 0) g_blocksum[blockIdx.x] = sh[0];
}

__global__ void scan_blockoffsets_kernel() {
    if (threadIdx.x == 0 && blockIdx.x == 0) {
        int run = 0;
        for (int i = 0; i < SCAN_NBLK; i++) {
            int t = g_blocksum[i];
            g_blocksum[i] = run;
            run += t;
        }
        g_blocksum[SCAN_NBLK] = run;
    }
}

__global__ __launch_bounds__(SCAN_B) void scan_offsets_kernel() {
    __shared__ int sh[SCAN_B];
    int i = blockIdx.x * SCAN_B + threadIdx.x;
    int v = (i < N_NODES) ? g_hist[i] : 0;
    sh[threadIdx.x] = v;
    __syncthreads();
    for (int s = 1; s < SCAN_B; s <<= 1) {
        int t = (threadIdx.x >= s) ? sh[threadIdx.x - s] : 0;
        __syncthreads();
        sh[threadIdx.x] += t;
        __syncthreads();
    }
    int excl = g_blocksum[blockIdx.x] + sh[threadIdx.x] - v;
    if (i < N_NODES) {
        g_off[i] = excl;
        g_cursor[i] = excl;
        if (i == N_NODES - 1) g_off[N_NODES] = excl + v;
    }
}

__global__ __launch_bounds__(256) void fill_kernel() {
    int e = blockIdx.x * blockDim.x + threadIdx.x;
    if (e >= N_EDGES) return;
    int pos = atomicAdd(&g_cursor[g_dst[e]], 1);
    g_srcs[pos] = g_src[e];
}

// ---------------- gather-mean aggregation (64-wide), unroll-4 for MLP --------
__global__ __launch_bounds__(256) void agg1_kernel(const float* __restrict__ x)
{
    int t = blockIdx.x * blockDim.x + threadIdx.x;
    int n = t >> 4;
    if (n >= N_NODES) return;
    int p4 = (t & 15) * 4;

    int beg = g_off[n], end = g_off[n + 1];
    float ax = 0.f, ay = 0.f, az = 0.f, aw = 0.f;

    int i = beg;
    for (; i + 3 < end; i += 4) {
        int s0 = g_srcs[i + 0];
        int s1 = g_srcs[i + 1];
        int s2 = g_srcs[i + 2];
        int s3 = g_srcs[i + 3];
        float4 v0 = *(const float4*)&x[s0 * 64 + p4];
        float4 v1 = *(const float4*)&x[s1 * 64 + p4];
        float4 v2 = *(const float4*)&x[s2 * 64 + p4];
        float4 v3 = *(const float4*)&x[s3 * 64 + p4];
        ax += (v0.x + v1.x) + (v2.x + v3.x);
        ay += (v0.y + v1.y) + (v2.y + v3.y);
        az += (v0.z + v1.z) + (v2.z + v3.z);
        aw += (v0.w + v1.w) + (v2.w + v3.w);
    }
    for (; i < end; i++) {
        int s0 = g_srcs[i];
        float4 v0 = *(const float4*)&x[s0 * 64 + p4];
        ax += v0.x; ay += v0.y; az += v0.z; aw += v0.w;
    }

    float inv = 1.f / fmaxf((float)(end - beg), 1.f);
    float4 o = make_float4(ax * inv, ay * inv, az * inv, aw * inv);
    *(float4*)&g_mean1[n * 64 + p4] = o;
}

__global__ __launch_bounds__(256) void agg2_kernel()
{
    int t = blockIdx.x * blockDim.x + threadIdx.x;
    int n = t >> 4;
    if (n >= N_NODES) return;
    int p4 = (t & 15) * 4;

    int beg = g_off[n], end = g_off[n + 1];
    float ax = 0.f, ay = 0.f, az = 0.f, aw = 0.f;

    int i = beg;
    for (; i + 3 < end; i += 4) {
        int s0 = g_srcs[i + 0];
        int s1 = g_srcs[i + 1];
        int s2 = g_srcs[i + 2];
        int s3 = g_srcs[i + 3];
        float4 v0 = *(const float4*)&g_hw[s0 * 64 + p4];
        float4 v1 = *(const float4*)&g_hw[s1 * 64 + p4];
        float4 v2 = *(const float4*)&g_hw[s2 * 64 + p4];
        float4 v3 = *(const float4*)&g_hw[s3 * 64 + p4];
        ax += (v0.x + v1.x) + (v2.x + v3.x);
        ay += (v0.y + v1.y) + (v2.y + v3.y);
        az += (v0.z + v1.z) + (v2.z + v3.z);
        aw += (v0.w + v1.w) + (v2.w + v3.w);
    }
    for (; i < end; i++) {
        int s0 = g_srcs[i];
        float4 v0 = *(const float4*)&g_hw[s0 * 64 + p4];
        ax += v0.x; ay += v0.y; az += v0.z; aw += v0.w;
    }

    float inv = 1.f / fmaxf((float)(end - beg), 1.f);
    float4 o = make_float4(ax * inv, ay * inv, az * inv, aw * inv);
    *(float4*)&g_mean2[n * 64 + p4] = o;
}

// ---------------- fused dense1 + hw projection -------------------------------
// 64-node tile, 256 threads.
//   GEMM1: h = relu(mean1 @ W1_l + x @ W1_r + b1)   (K=64 -> 128)
//   GEMM2: hw = h @ W2_l                            (K=128 -> 64)
// h tile kept in smem (aliased over input tiles) between the two GEMMs.
__global__ __launch_bounds__(256) void dense1_fused_kernel(
    const float* __restrict__ x,
    const float* __restrict__ Wl,
    const float* __restrict__ Wr,
    const float* __restrict__ b,
    const float* __restrict__ W2l)
{
    extern __shared__ float sh[];
    float* sWl = sh;                   // 64*128 = 8192
    float* sWr = sWl + 64 * 128;       // 8192
    float* sW2 = sWr + 64 * 128;       // 128*64 = 8192
    float* sB  = sW2 + 128 * 64;       // 128
    float* sMX = sB + 128;             // 64*64*2 = 8192 (sM | sX), later sH 64*128

    float* sM = sMX;
    float* sX = sMX + 64 * 64;
    float* sH = sMX;                   // alias after GEMM1

    const int tid = threadIdx.x;
    for (int i = tid; i < 64 * 128; i += 256) {
        sWl[i] = Wl[i];
        sWr[i] = Wr[i];
        sW2[i] = W2l[i];
    }
    if (tid < 128) sB[tid] = b[tid];

    const int node0 = blockIdx.x * 64;
    for (int i = tid; i < 64 * 64; i += 256) {
        int ln = i >> 6, f = i & 63;
        int n = node0 + ln;
        if (n < N_NODES) {
            sM[i] = g_mean1[n * 64 + f];
            sX[i] = x[n * 64 + f];
        } else { sM[i] = 0.f; sX[i] = 0.f; }
    }
    __syncthreads();

    // ---- GEMM1: 8 nodes x 4 cols per thread ----
    const int c4 = (tid & 31) * 4;     // 0..124
    const int ng = tid >> 5;           // 0..7 -> nodes ng*8 .. ng*8+7
    float acc[8][4];
    #pragma unroll
    for (int i = 0; i < 8; i++)
        #pragma unroll
        for (int j = 0; j < 4; j++) acc[i][j] = 0.f;

    #pragma unroll 4
    for (int k = 0; k < 64; k += 4) {
        float4 mv[8], xv[8];
        #pragma unroll
        for (int i = 0; i < 8; i++) {
            int ln = ng * 8 + i;
            mv[i] = *(const float4*)&sM[ln * 64 + k];
            xv[i] = *(const float4*)&sX[ln * 64 + k];
        }
        #pragma unroll
        for (int kk = 0; kk < 4; kk++) {
            float4 wl = *(const float4*)&sWl[(k + kk) * 128 + c4];
            float4 wr = *(const float4*)&sWr[(k + kk) * 128 + c4];
            #pragma unroll
            for (int i = 0; i < 8; i++) {
                float m  = (&mv[i].x)[kk];
                float xx = (&xv[i].x)[kk];
                acc[i][0] += wl.x * m + wr.x * xx;
                acc[i][1] += wl.y * m + wr.y * xx;
                acc[i][2] += wl.z * m + wr.z * xx;
                acc[i][3] += wl.w * m + wr.w * xx;
            }
        }
    }

    float hreg[8][4];
    #pragma unroll
    for (int i = 0; i < 8; i++) {
        hreg[i][0] = fmaxf(acc[i][0] + sB[c4 + 0], 0.f);
        hreg[i][1] = fmaxf(acc[i][1] + sB[c4 + 1], 0.f);
        hreg[i][2] = fmaxf(acc[i][2] + sB[c4 + 2], 0.f);
        hreg[i][3] = fmaxf(acc[i][3] + sB[c4 + 3], 0.f);
    }

    __syncthreads();   // everyone done reading sM/sX

    #pragma unroll
    for (int i = 0; i < 8; i++) {
        int ln = ng * 8 + i;
        int n = node0 + ln;
        float4 o = make_float4(hreg[i][0], hreg[i][1], hreg[i][2], hreg[i][3]);
        *(float4*)&sH[ln * 128 + c4] = o;
        if (n < N_NODES) *(float4*)&g_h[n * 128 + c4] = o;
    }
    __syncthreads();

    // ---- GEMM2: hw = h @ W2_l : 4 nodes x 4 cols per thread ----
    const int c4b = (tid & 15) * 4;    // 0..60
    const int ngb = tid >> 4;          // 0..15 -> nodes ngb*4 .. ngb*4+3
    float acc2[4][4];
    #pragma unroll
    for (int i = 0; i < 4; i++)
        #pragma unroll
        for (int j = 0; j < 4; j++) acc2[i][j] = 0.f;

    #pragma unroll 4
    for (int k = 0; k < 128; k += 4) {
        float4 hv[4];
        #pragma unroll
        for (int i = 0; i < 4; i++)
            hv[i] = *(const float4*)&sH[(ngb * 4 + i) * 128 + k];
        #pragma unroll
        for (int kk = 0; kk < 4; kk++) {
            float4 w = *(const float4*)&sW2[(k + kk) * 64 + c4b];
            #pragma unroll
            for (int i = 0; i < 4; i++) {
                float hh = (&hv[i].x)[kk];
                acc2[i][0] += w.x * hh;
                acc2[i][1] += w.y * hh;
                acc2[i][2] += w.z * hh;
                acc2[i][3] += w.w * hh;
            }
        }
    }

    #pragma unroll
    for (int i = 0; i < 4; i++) {
        int n = node0 + ngb * 4 + i;
        if (n < N_NODES) {
            float4 o = make_float4(acc2[i][0], acc2[i][1], acc2[i][2], acc2[i][3]);
            *(float4*)&g_hw[n * 64 + c4b] = o;
        }
    }
}

// ---------------- final dense2: out = mean2 + h @ W2_r + b2 ------------------
// 128-node tile, 256 threads, 8 nodes x 4 cols per thread (FMA-bound).
__global__ __launch_bounds__(256) void dense2_kernel(
    const float* __restrict__ Wr,
    const float* __restrict__ b,
    float* __restrict__ out)
{
    extern __shared__ float sh[];
    float* sW = sh;                    // 128*64 = 8192
    float* sH = sW + 128 * 64;         // 128*128 = 16384
    float* sB = sH + 128 * 128;        // 64

    const int tid = threadIdx.x;
    for (int i = tid; i < 128 * 64; i += 256) sW[i] = Wr[i];
    if (tid < 64) sB[tid] = b[tid];

    const int node0 = blockIdx.x * 128;
    for (int i = tid; i < 128 * 128 / 4; i += 256) {
        int ln = i >> 5;               // /32 float4s per row
        int f4 = (i & 31) * 4;
        int n = node0 + ln;
        float4 v = (n < N_NODES) ? *(const float4*)&g_h[n * 128 + f4]
                                 : make_float4(0.f, 0.f, 0.f, 0.f);
        *(float4*)&sH[ln * 128 + f4] = v;
    }
    __syncthreads();

    const int c4 = (tid & 15) * 4;     // 0..60
    const int ng = tid >> 4;           // 0..15 -> nodes ng*8 .. ng*8+7
    float acc[8][4];
    #pragma unroll
    for (int i = 0; i < 8; i++)
        #pragma unroll
        for (int j = 0; j < 4; j++) acc[i][j] = 0.f;

    #pragma unroll 4
    for (int k = 0; k < 128; k += 4) {
        float4 hv[8];
        #pragma unroll
        for (int i = 0; i < 8; i++)
            hv[i] = *(const float4*)&sH[(ng * 8 + i) * 128 + k];
        #pragma unroll
        for (int kk = 0; kk < 4; kk++) {
            float4 w = *(const float4*)&sW[(k + kk) * 64 + c4];
            #pragma unroll
            for (int i = 0; i < 8; i++) {
                float hh = (&hv[i].x)[kk];
                acc[i][0] += w.x * hh;
                acc[i][1] += w.y * hh;
                acc[i][2] += w.z * hh;
                acc[i][3] += w.w * hh;
            }
        }
    }

    #pragma unroll
    for (int i = 0; i < 8; i++) {
        int n = node0 + ng * 8 + i;
        if (n < N_NODES) {
            float4 m = *(const float4*)&g_mean2[n * 64 + c4];
            float4 o;
            o.x = acc[i][0] + m.x + sB[c4 + 0];
            o.y = acc[i][1] + m.y + sB[c4 + 1];
            o.z = acc[i][2] + m.z + sB[c4 + 2];
            o.w = acc[i][3] + m.w + sB[c4 + 3];
            *(float4*)&out[n * 64 + c4] = o;
        }
    }
}

// ---------------- launch ----------------------------------------------------
extern "C" void kernel_launch(void* const* d_in, const int* in_sizes, int n_in,
                              void* d_out, int out_size)
{
    const float* x   = (const float*)d_in[0];
    const void*  ei  = d_in[1];
    const float* W1l = (const float*)d_in[2];
    const float* W1r = (const float*)d_in[3];
    const float* b1  = (const float*)d_in[4];
    const float* W2l = (const float*)d_in[5];
    const float* W2r = (const float*)d_in[6];
    const float* b2  = (const float*)d_in[7];
    float* out = (float*)d_out;

    const int d1_smem = (64 * 128 * 3 + 128 + 64 * 128) * (int)sizeof(float);   // 131584
    const int d2_smem = (128 * 64 + 128 * 128 + 64) * (int)sizeof(float);       //  98560
    cudaFuncSetAttribute(dense1_fused_kernel, cudaFuncAttributeMaxDynamicSharedMemorySize, d1_smem);
    cudaFuncSetAttribute(dense2_kernel,       cudaFuncAttributeMaxDynamicSharedMemorySize, d2_smem);

    // --- edge-index dtype detection + CSR build ---
    detect_kernel<<<1, 32>>>(ei);
    zero_hist_kernel<<<(N_NODES + 1023) / 1024, 1024>>>();
    convert_hist_kernel<<<(N_EDGES + 255) / 256, 256>>>(ei);
    scan_blocksums_kernel<<<SCAN_NBLK, SCAN_B>>>();
    scan_blockoffsets_kernel<<<1, 32>>>();
    scan_offsets_kernel<<<SCAN_NBLK, SCAN_B>>>();
    fill_kernel<<<(N_EDGES + 255) / 256, 256>>>();

    // --- layer 1 (+ hw projection fused) ---
    agg1_kernel<<<(N_NODES * 16 + 255) / 256, 256>>>(x);
    dense1_fused_kernel<<<(N_NODES + 63) / 64, 256, d1_smem>>>(x, W1l, W1r, b1, W2l);

    // --- layer 2 ---
    agg2_kernel<<<(N_NODES * 16 + 255) / 256, 256>>>();
    dense2_kernel<<<(N_NODES + 127) / 128, 256, d2_smem>>>(W2r, b2, out);
}

// round 12
// speedup vs baseline: 1.2758x; 1.1559x over previous
#include <cuda_runtime.h>
#include <cuda_bf16.h>

#define N_NODES 100000
#define N_EDGES 1600000
#define SCAN_B  512
#define SCAN_NBLK ((N_NODES + SCAN_B - 1) / SCAN_B)   // 196

// ---------------- scratch (device globals; referenced ONLY in device code) ---
__device__ int   g_is64;
__device__ int   g_src   [N_EDGES];
__device__ int   g_dst   [N_EDGES];
__device__ int   g_hist  [N_NODES];
__device__ int   g_off   [N_NODES + 1];
__device__ int   g_cursor[N_NODES];
__device__ int   g_blocksum[SCAN_NBLK + 1];
__device__ int   g_srcs  [N_EDGES];       // CSR adjacency (source per slot)
__device__ float g_mean1 [N_NODES * 64];
__device__ float g_hw    [N_NODES * 64];  // h @ W2_l
__device__ float g_hr    [N_NODES * 64];  // h @ W2_r + b2

// ---------------- dtype detection -------------------------------------------
__global__ void detect_kernel(const void* __restrict__ ei_raw) {
    if (threadIdx.x == 0 && blockIdx.x == 0) {
        const unsigned long long* p = (const unsigned long long*)ei_raw;
        int is64 = 1;
        for (int i = 0; i < 64; i++)
            if (p[i] >= (1ULL << 32)) { is64 = 0; break; }
        g_is64 = is64;
    }
}

__device__ __forceinline__ int clamp_idx(long long v) {
    if (v < 0) return 0;
    if (v >= N_NODES) return N_NODES - 1;
    return (int)v;
}

__global__ void zero_hist_kernel() {
    int i = blockIdx.x * blockDim.x + threadIdx.x;
    if (i < N_NODES) g_hist[i] = 0;
}

// fused convert + degree histogram (single pass over edge list)
__global__ __launch_bounds__(256) void convert_hist_kernel(const void* __restrict__ ei_raw) {
    int e = blockIdx.x * blockDim.x + threadIdx.x;
    if (e >= N_EDGES) return;
    int s, d;
    if (g_is64) {
        const long long* p = (const long long*)ei_raw;
        s = clamp_idx(p[e]);
        d = clamp_idx(p[N_EDGES + e]);
    } else {
        const int* p = (const int*)ei_raw;
        s = clamp_idx((long long)p[e]);
        d = clamp_idx((long long)p[N_EDGES + e]);
    }
    g_src[e] = s;
    g_dst[e] = d;
    atomicAdd(&g_hist[d], 1);
}

// ---------------- CSR scan + fill -------------------------------------------
__global__ __launch_bounds__(SCAN_B) void scan_blocksums_kernel() {
    __shared__ int sh[SCAN_B];
    int i = blockIdx.x * SCAN_B + threadIdx.x;
    sh[threadIdx.x] = (i < N_NODES) ? g_hist[i] : 0;
    __syncthreads();
    for (int s = SCAN_B / 2; s > 0; s >>= 1) {
        if (threadIdx.x < s) sh[threadIdx.x] += sh[threadIdx.x + s];
        __syncthreads();
    }
    if (threadIdx.x == 0) g_blocksum[blockIdx.x] = sh[0];
}

__global__ void scan_blockoffsets_kernel() {
    if (threadIdx.x == 0 && blockIdx.x == 0) {
        int run = 0;
        for (int i = 0; i < SCAN_NBLK; i++) {
            int t = g_blocksum[i];
            g_blocksum[i] = run;
            run += t;
        }
        g_blocksum[SCAN_NBLK] = run;
    }
}

__global__ __launch_bounds__(SCAN_B) void scan_offsets_kernel() {
    __shared__ int sh[SCAN_B];
    int i = blockIdx.x * SCAN_B + threadIdx.x;
    int v = (i < N_NODES) ? g_hist[i] : 0;
    sh[threadIdx.x] = v;
    __syncthreads();
    for (int s = 1; s < SCAN_B; s <<= 1) {
        int t = (threadIdx.x >= s) ? sh[threadIdx.x - s] : 0;
        __syncthreads();
        sh[threadIdx.x] += t;
        __syncthreads();
    }
    int excl = g_blocksum[blockIdx.x] + sh[threadIdx.x] - v;
    if (i < N_NODES) {
        g_off[i] = excl;
        g_cursor[i] = excl;
        if (i == N_NODES - 1) g_off[N_NODES] = excl + v;
    }
}

__global__ __launch_bounds__(256) void fill_kernel() {
    int e = blockIdx.x * blockDim.x + threadIdx.x;
    if (e >= N_EDGES) return;
    int pos = atomicAdd(&g_cursor[g_dst[e]], 1);
    g_srcs[pos] = g_src[e];
}

// ---------------- gather-mean aggregation layer 1 (x -> g_mean1) -------------
__global__ __launch_bounds__(256) void agg1_kernel(const float* __restrict__ x)
{
    int t = blockIdx.x * blockDim.x + threadIdx.x;
    int n = t >> 4;
    if (n >= N_NODES) return;
    int p4 = (t & 15) * 4;

    int beg = g_off[n], end = g_off[n + 1];
    float ax = 0.f, ay = 0.f, az = 0.f, aw = 0.f;

    int i = beg;
    for (; i + 3 < end; i += 4) {
        int s0 = g_srcs[i + 0];
        int s1 = g_srcs[i + 1];
        int s2 = g_srcs[i + 2];
        int s3 = g_srcs[i + 3];
        float4 v0 = *(const float4*)&x[s0 * 64 + p4];
        float4 v1 = *(const float4*)&x[s1 * 64 + p4];
        float4 v2 = *(const float4*)&x[s2 * 64 + p4];
        float4 v3 = *(const float4*)&x[s3 * 64 + p4];
        ax += (v0.x + v1.x) + (v2.x + v3.x);
        ay += (v0.y + v1.y) + (v2.y + v3.y);
        az += (v0.z + v1.z) + (v2.z + v3.z);
        aw += (v0.w + v1.w) + (v2.w + v3.w);
    }
    for (; i < end; i++) {
        int s0 = g_srcs[i];
        float4 v0 = *(const float4*)&x[s0 * 64 + p4];
        ax += v0.x; ay += v0.y; az += v0.z; aw += v0.w;
    }

    float inv = 1.f / fmaxf((float)(end - beg), 1.f);
    float4 o = make_float4(ax * inv, ay * inv, az * inv, aw * inv);
    *(float4*)&g_mean1[n * 64 + p4] = o;
}

// ---------------- agg2 + final add: out = mean(g_hw over nbrs) + g_hr --------
__global__ __launch_bounds__(256) void agg2_final_kernel(float* __restrict__ out)
{
    int t = blockIdx.x * blockDim.x + threadIdx.x;
    int n = t >> 4;
    if (n >= N_NODES) return;
    int p4 = (t & 15) * 4;

    int beg = g_off[n], end = g_off[n + 1];
    float ax = 0.f, ay = 0.f, az = 0.f, aw = 0.f;

    int i = beg;
    for (; i + 3 < end; i += 4) {
        int s0 = g_srcs[i + 0];
        int s1 = g_srcs[i + 1];
        int s2 = g_srcs[i + 2];
        int s3 = g_srcs[i + 3];
        float4 v0 = *(const float4*)&g_hw[s0 * 64 + p4];
        float4 v1 = *(const float4*)&g_hw[s1 * 64 + p4];
        float4 v2 = *(const float4*)&g_hw[s2 * 64 + p4];
        float4 v3 = *(const float4*)&g_hw[s3 * 64 + p4];
        ax += (v0.x + v1.x) + (v2.x + v3.x);
        ay += (v0.y + v1.y) + (v2.y + v3.y);
        az += (v0.z + v1.z) + (v2.z + v3.z);
        aw += (v0.w + v1.w) + (v2.w + v3.w);
    }
    for (; i < end; i++) {
        int s0 = g_srcs[i];
        float4 v0 = *(const float4*)&g_hw[s0 * 64 + p4];
        ax += v0.x; ay += v0.y; az += v0.z; aw += v0.w;
    }

    float inv = 1.f / fmaxf((float)(end - beg), 1.f);
    float4 r = *(const float4*)&g_hr[n * 64 + p4];
    float4 o;
    o.x = ax * inv + r.x;
    o.y = ay * inv + r.y;
    o.z = az * inv + r.z;
    o.w = aw * inv + r.w;
    *(float4*)&out[n * 64 + p4] = o;
}

// ---------------- fused dense: all three GEMMs, h never leaves smem ----------
// 64-node tile, 256 threads.
//   GEMM1: h  = relu(mean1 @ W1_l + x @ W1_r + b1)   (K=64  -> 128), h -> smem
//   GEMM2: hw = h @ W2_l                             (K=128 -> 64)  -> g_hw
//          hr = h @ W2_r + b2                        (K=128 -> 64)  -> g_hr
__global__ __launch_bounds__(256) void dense_fused_kernel(
    const float* __restrict__ x,
    const float* __restrict__ W1l,
    const float* __restrict__ W1r,
    const float* __restrict__ b1,
    const float* __restrict__ W2l,
    const float* __restrict__ W2r,
    const float* __restrict__ b2)
{
    extern __shared__ float sh[];
    float* sWl  = sh;                   // 64*128 = 8192
    float* sWr  = sWl + 64 * 128;       // 8192
    float* sW2l = sWr + 64 * 128;       // 128*64 = 8192
    float* sW2r = sW2l + 128 * 64;      // 8192
    float* sB1  = sW2r + 128 * 64;      // 128
    float* sB2  = sB1 + 128;            // 64
    float* sMX  = sB2 + 64;             // 64*64*2 = 8192 (sM | sX), later sH 64*128

    float* sM = sMX;
    float* sX = sMX + 64 * 64;
    float* sH = sMX;                    // alias after GEMM1

    const int tid = threadIdx.x;
    for (int i = tid; i < 64 * 128; i += 256) {
        sWl[i]  = W1l[i];
        sWr[i]  = W1r[i];
        sW2l[i] = W2l[i];
        sW2r[i] = W2r[i];
    }
    if (tid < 128) sB1[tid] = b1[tid];
    if (tid >= 128 && tid < 192) sB2[tid - 128] = b2[tid - 128];

    const int node0 = blockIdx.x * 64;
    for (int i = tid; i < 64 * 64; i += 256) {
        int ln = i >> 6, f = i & 63;
        int n = node0 + ln;
        if (n < N_NODES) {
            sM[i] = g_mean1[n * 64 + f];
            sX[i] = x[n * 64 + f];
        } else { sM[i] = 0.f; sX[i] = 0.f; }
    }
    __syncthreads();

    // ---- GEMM1: 8 nodes x 4 cols per thread (warp-broadcast A loads) ----
    const int c4 = (tid & 31) * 4;     // 0..124
    const int ng = tid >> 5;           // 0..7 -> nodes ng*8 .. ng*8+7
    float acc[8][4];
    #pragma unroll
    for (int i = 0; i < 8; i++)
        #pragma unroll
        for (int j = 0; j < 4; j++) acc[i][j] = 0.f;

    #pragma unroll 4
    for (int k = 0; k < 64; k += 4) {
        float4 mv[8], xv[8];
        #pragma unroll
        for (int i = 0; i < 8; i++) {
            int ln = ng * 8 + i;
            mv[i] = *(const float4*)&sM[ln * 64 + k];
            xv[i] = *(const float4*)&sX[ln * 64 + k];
        }
        #pragma unroll
        for (int kk = 0; kk < 4; kk++) {
            float4 wl = *(const float4*)&sWl[(k + kk) * 128 + c4];
            float4 wr = *(const float4*)&sWr[(k + kk) * 128 + c4];
            #pragma unroll
            for (int i = 0; i < 8; i++) {
                float m  = (&mv[i].x)[kk];
                float xx = (&xv[i].x)[kk];
                acc[i][0] += wl.x * m + wr.x * xx;
                acc[i][1] += wl.y * m + wr.y * xx;
                acc[i][2] += wl.z * m + wr.z * xx;
                acc[i][3] += wl.w * m + wr.w * xx;
            }
        }
    }

    float hreg[8][4];
    #pragma unroll
    for (int i = 0; i < 8; i++) {
        hreg[i][0] = fmaxf(acc[i][0] + sB1[c4 + 0], 0.f);
        hreg[i][1] = fmaxf(acc[i][1] + sB1[c4 + 1], 0.f);
        hreg[i][2] = fmaxf(acc[i][2] + sB1[c4 + 2], 0.f);
        hreg[i][3] = fmaxf(acc[i][3] + sB1[c4 + 3], 0.f);
    }

    __syncthreads();   // everyone done reading sM/sX

    #pragma unroll
    for (int i = 0; i < 8; i++) {
        int ln = ng * 8 + i;
        *(float4*)&sH[ln * 128 + c4] =
            make_float4(hreg[i][0], hreg[i][1], hreg[i][2], hreg[i][3]);
    }
    __syncthreads();

    // ---- GEMM2: hw = h@W2l, hr = h@W2r + b2 : 4 nodes x 4 cols x 2 mats ----
    const int c4b = (tid & 15) * 4;    // 0..60
    const int ngb = tid >> 4;          // 0..15 -> nodes ngb*4 .. ngb*4+3
    float aw2[4][4], ar2[4][4];
    #pragma unroll
    for (int i = 0; i < 4; i++)
        #pragma unroll
        for (int j = 0; j < 4; j++) { aw2[i][j] = 0.f; ar2[i][j] = 0.f; }

    #pragma unroll 4
    for (int k = 0; k < 128; k += 4) {
        float4 hv[4];
        #pragma unroll
        for (int i = 0; i < 4; i++)
            hv[i] = *(const float4*)&sH[(ngb * 4 + i) * 128 + k];
        #pragma unroll
        for (int kk = 0; kk < 4; kk++) {
            float4 wl = *(const float4*)&sW2l[(k + kk) * 64 + c4b];
            float4 wr = *(const float4*)&sW2r[(k + kk) * 64 + c4b];
            #pragma unroll
            for (int i = 0; i < 4; i++) {
                float hh = (&hv[i].x)[kk];
                aw2[i][0] += wl.x * hh;
                aw2[i][1] += wl.y * hh;
                aw2[i][2] += wl.z * hh;
                aw2[i][3] += wl.w * hh;
                ar2[i][0] += wr.x * hh;
                ar2[i][1] += wr.y * hh;
                ar2[i][2] += wr.z * hh;
                ar2[i][3] += wr.w * hh;
            }
        }
    }

    #pragma unroll
    for (int i = 0; i < 4; i++) {
        int n = node0 + ngb * 4 + i;
        if (n < N_NODES) {
            *(float4*)&g_hw[n * 64 + c4b] =
                make_float4(aw2[i][0], aw2[i][1], aw2[i][2], aw2[i][3]);
            float4 r;
            r.x = ar2[i][0] + sB2[c4b + 0];
            r.y = ar2[i][1] + sB2[c4b + 1];
            r.z = ar2[i][2] + sB2[c4b + 2];
            r.w = ar2[i][3] + sB2[c4b + 3];
            *(float4*)&g_hr[n * 64 + c4b] = r;
        }
    }
}

// ---------------- launch ----------------------------------------------------
extern "C" void kernel_launch(void* const* d_in, const int* in_sizes, int n_in,
                              void* d_out, int out_size)
{
    const float* x   = (const float*)d_in[0];
    const void*  ei  = d_in[1];
    const float* W1l = (const float*)d_in[2];
    const float* W1r = (const float*)d_in[3];
    const float* b1  = (const float*)d_in[4];
    const float* W2l = (const float*)d_in[5];
    const float* W2r = (const float*)d_in[6];
    const float* b2  = (const float*)d_in[7];
    float* out = (float*)d_out;

    // 4 weight mats (4*8192) + biases (192) + input/h tile (8192) floats
    const int df_smem = (64 * 128 * 4 + 192 + 64 * 128) * (int)sizeof(float);   // 164608
    cudaFuncSetAttribute(dense_fused_kernel, cudaFuncAttributeMaxDynamicSharedMemorySize, df_smem);

    // --- edge-index dtype detection + CSR build ---
    detect_kernel<<<1, 32>>>(ei);
    zero_hist_kernel<<<(N_NODES + 1023) / 1024, 1024>>>();
    convert_hist_kernel<<<(N_EDGES + 255) / 256, 256>>>(ei);
    scan_blocksums_kernel<<<SCAN_NBLK, SCAN_B>>>();
    scan_blockoffsets_kernel<<<1, 32>>>();
    scan_offsets_kernel<<<SCAN_NBLK, SCAN_B>>>();
    fill_kernel<<<(N_EDGES + 255) / 256, 256>>>();

    // --- layer 1 aggregation ---
    agg1_kernel<<<(N_NODES * 16 + 255) / 256, 256>>>(x);

    // --- all dense work in one kernel (h stays in smem) ---
    dense_fused_kernel<<<(N_NODES + 63) / 64, 256, df_smem>>>(x, W1l, W1r, b1, W2l, W2r, b2);

    // --- layer 2 aggregation + final add ---
    agg2_final_kernel<<<(N_NODES * 16 + 255) / 256, 256>>>(out);
}

// round 13
// speedup vs baseline: 1.3800x; 1.0817x over previous
#include <cuda_runtime.h>
#include <cuda_bf16.h>

#define N_NODES 100000
#define N_EDGES 1600000
#define SCAN_B  512
#define SCAN_NBLK ((N_NODES + SCAN_B - 1) / SCAN_B)   // 196

// ---------------- scratch (device globals; referenced ONLY in device code) ---
__device__ int   g_is64;
__device__ int   g_src   [N_EDGES];
__device__ int   g_dst   [N_EDGES];
__device__ int   g_hist  [N_NODES];
__device__ int   g_off   [N_NODES + 1];
__device__ int   g_cursor[N_NODES];
__device__ int   g_blocksum[SCAN_NBLK + 1];
__device__ int   g_srcs  [N_EDGES];       // CSR adjacency (source per slot)
__device__ float g_mean1 [N_NODES * 64];
__device__ float g_hw    [N_NODES * 64];  // h @ W2_l
__device__ float g_hr    [N_NODES * 64];  // h @ W2_r + b2

// ---------------- packed f32x2 helpers (Blackwell) ---------------------------
__device__ __forceinline__ unsigned long long pack2(float lo, float hi) {
    unsigned long long r;
    asm("mov.b64 %0, {%1, %2};" : "=l"(r) : "f"(lo), "f"(hi));
    return r;
}
__device__ __forceinline__ void fma2(unsigned long long& d,
                                     unsigned long long a, unsigned long long b) {
    asm("fma.rn.f32x2 %0, %1, %2, %0;" : "+l"(d) : "l"(a), "l"(b));
}
__device__ __forceinline__ float2 unpack2(unsigned long long v) {
    float lo, hi;
    asm("mov.b64 {%0, %1}, %2;" : "=f"(lo), "=f"(hi) : "l"(v));
    return make_float2(lo, hi);
}

// ---------------- dtype detection -------------------------------------------
__global__ void detect_kernel(const void* __restrict__ ei_raw) {
    if (threadIdx.x == 0 && blockIdx.x == 0) {
        const unsigned long long* p = (const unsigned long long*)ei_raw;
        int is64 = 1;
        for (int i = 0; i < 64; i++)
            if (p[i] >= (1ULL << 32)) { is64 = 0; break; }
        g_is64 = is64;
    }
}

__device__ __forceinline__ int clamp_idx(long long v) {
    if (v < 0) return 0;
    if (v >= N_NODES) return N_NODES - 1;
    return (int)v;
}

__global__ void zero_hist_kernel() {
    int i = blockIdx.x * blockDim.x + threadIdx.x;
    if (i < N_NODES) g_hist[i] = 0;
}

// fused convert + degree histogram (single pass over edge list)
__global__ __launch_bounds__(256) void convert_hist_kernel(const void* __restrict__ ei_raw) {
    int e = blockIdx.x * blockDim.x + threadIdx.x;
    if (e >= N_EDGES) return;
    int s, d;
    if (g_is64) {
        const long long* p = (const long long*)ei_raw;
        s = clamp_idx(p[e]);
        d = clamp_idx(p[N_EDGES + e]);
    } else {
        const int* p = (const int*)ei_raw;
        s = clamp_idx((long long)p[e]);
        d = clamp_idx((long long)p[N_EDGES + e]);
    }
    g_src[e] = s;
    g_dst[e] = d;
    atomicAdd(&g_hist[d], 1);
}

// ---------------- CSR scan + fill -------------------------------------------
__global__ __launch_bounds__(SCAN_B) void scan_blocksums_kernel() {
    __shared__ int sh[SCAN_B];
    int i = blockIdx.x * SCAN_B + threadIdx.x;
    sh[threadIdx.x] = (i < N_NODES) ? g_hist[i] : 0;
    __syncthreads();
    for (int s = SCAN_B / 2; s > 0; s >>= 1) {
        if (threadIdx.x < s) sh[threadIdx.x] += sh[threadIdx.x + s];
        __syncthreads();
    }
    if (threadIdx.x == 0) g_blocksum[blockIdx.x] = sh[0];
}

__global__ void scan_blockoffsets_kernel() {
    if (threadIdx.x == 0 && blockIdx.x == 0) {
        int run = 0;
        for (int i = 0; i < SCAN_NBLK; i++) {
            int t = g_blocksum[i];
            g_blocksum[i] = run;
            run += t;
        }
        g_blocksum[SCAN_NBLK] = run;
    }
}

__global__ __launch_bounds__(SCAN_B) void scan_offsets_kernel() {
    __shared__ int sh[SCAN_B];
    int i = blockIdx.x * SCAN_B + threadIdx.x;
    int v = (i < N_NODES) ? g_hist[i] : 0;
    sh[threadIdx.x] = v;
    __syncthreads();
    for (int s = 1; s < SCAN_B; s <<= 1) {
        int t = (threadIdx.x >= s) ? sh[threadIdx.x - s] : 0;
        __syncthreads();
        sh[threadIdx.x] += t;
        __syncthreads();
    }
    int excl = g_blocksum[blockIdx.x] + sh[threadIdx.x] - v;
    if (i < N_NODES) {
        g_off[i] = excl;
        g_cursor[i] = excl;
        if (i == N_NODES - 1) g_off[N_NODES] = excl + v;
    }
}

__global__ __launch_bounds__(256) void fill_kernel() {
    int e = blockIdx.x * blockDim.x + threadIdx.x;
    if (e >= N_EDGES) return;
    int pos = atomicAdd(&g_cursor[g_dst[e]], 1);
    g_srcs[pos] = g_src[e];
}

// ---------------- gather-mean aggregation layer 1 (x -> g_mean1) -------------
__global__ __launch_bounds__(256) void agg1_kernel(const float* __restrict__ x)
{
    int t = blockIdx.x * blockDim.x + threadIdx.x;
    int n = t >> 4;
    if (n >= N_NODES) return;
    int p4 = (t & 15) * 4;

    int beg = g_off[n], end = g_off[n + 1];
    float ax = 0.f, ay = 0.f, az = 0.f, aw = 0.f;

    int i = beg;
    for (; i + 3 < end; i += 4) {
        int s0 = g_srcs[i + 0];
        int s1 = g_srcs[i + 1];
        int s2 = g_srcs[i + 2];
        int s3 = g_srcs[i + 3];
        float4 v0 = *(const float4*)&x[s0 * 64 + p4];
        float4 v1 = *(const float4*)&x[s1 * 64 + p4];
        float4 v2 = *(const float4*)&x[s2 * 64 + p4];
        float4 v3 = *(const float4*)&x[s3 * 64 + p4];
        ax += (v0.x + v1.x) + (v2.x + v3.x);
        ay += (v0.y + v1.y) + (v2.y + v3.y);
        az += (v0.z + v1.z) + (v2.z + v3.z);
        aw += (v0.w + v1.w) + (v2.w + v3.w);
    }
    for (; i < end; i++) {
        int s0 = g_srcs[i];
        float4 v0 = *(const float4*)&x[s0 * 64 + p4];
        ax += v0.x; ay += v0.y; az += v0.z; aw += v0.w;
    }

    float inv = 1.f / fmaxf((float)(end - beg), 1.f);
    float4 o = make_float4(ax * inv, ay * inv, az * inv, aw * inv);
    *(float4*)&g_mean1[n * 64 + p4] = o;
}

// ---------------- agg2 + final add: out = mean(g_hw over nbrs) + g_hr --------
__global__ __launch_bounds__(256) void agg2_final_kernel(float* __restrict__ out)
{
    int t = blockIdx.x * blockDim.x + threadIdx.x;
    int n = t >> 4;
    if (n >= N_NODES) return;
    int p4 = (t & 15) * 4;

    int beg = g_off[n], end = g_off[n + 1];
    float ax = 0.f, ay = 0.f, az = 0.f, aw = 0.f;

    int i = beg;
    for (; i + 3 < end; i += 4) {
        int s0 = g_srcs[i + 0];
        int s1 = g_srcs[i + 1];
        int s2 = g_srcs[i + 2];
        int s3 = g_srcs[i + 3];
        float4 v0 = *(const float4*)&g_hw[s0 * 64 + p4];
        float4 v1 = *(const float4*)&g_hw[s1 * 64 + p4];
        float4 v2 = *(const float4*)&g_hw[s2 * 64 + p4];
        float4 v3 = *(const float4*)&g_hw[s3 * 64 + p4];
        ax += (v0.x + v1.x) + (v2.x + v3.x);
        ay += (v0.y + v1.y) + (v2.y + v3.y);
        az += (v0.z + v1.z) + (v2.z + v3.z);
        aw += (v0.w + v1.w) + (v2.w + v3.w);
    }
    for (; i < end; i++) {
        int s0 = g_srcs[i];
        float4 v0 = *(const float4*)&g_hw[s0 * 64 + p4];
        ax += v0.x; ay += v0.y; az += v0.z; aw += v0.w;
    }

    float inv = 1.f / fmaxf((float)(end - beg), 1.f);
    float4 r = *(const float4*)&g_hr[n * 64 + p4];
    float4 o;
    o.x = ax * inv + r.x;
    o.y = ay * inv + r.y;
    o.z = az * inv + r.z;
    o.w = aw * inv + r.w;
    *(float4*)&out[n * 64 + p4] = o;
}

// ---------------- fused dense: all three GEMMs, h never leaves smem ----------
// 64-node tile, 256 threads, f32x2 packed FMA (2 fp32 FMA / instr).
//   GEMM1: h  = relu(mean1 @ W1_l + x @ W1_r + b1)   (K=64  -> 128), h -> smem
//   GEMM2: hw = h @ W2_l                             (K=128 -> 64)  -> g_hw
//          hr = h @ W2_r + b2                        (K=128 -> 64)  -> g_hr
__global__ __launch_bounds__(256) void dense_fused_kernel(
    const float* __restrict__ x,
    const float* __restrict__ W1l,
    const float* __restrict__ W1r,
    const float* __restrict__ b1,
    const float* __restrict__ W2l,
    const float* __restrict__ W2r,
    const float* __restrict__ b2)
{
    extern __shared__ float sh[];
    float* sWl  = sh;                   // 64*128 = 8192
    float* sWr  = sWl + 64 * 128;       // 8192
    float* sW2l = sWr + 64 * 128;       // 128*64 = 8192
    float* sW2r = sW2l + 128 * 64;      // 8192
    float* sB1  = sW2r + 128 * 64;      // 128
    float* sB2  = sB1 + 128;            // 64
    float* sMX  = sB2 + 64;             // 64*64*2 = 8192 (sM | sX), later sH 64*128

    float* sM = sMX;
    float* sX = sMX + 64 * 64;
    float* sH = sMX;                    // alias after GEMM1

    const int tid = threadIdx.x;
    for (int i = tid; i < 64 * 128; i += 256) {
        sWl[i]  = W1l[i];
        sWr[i]  = W1r[i];
        sW2l[i] = W2l[i];
        sW2r[i] = W2r[i];
    }
    if (tid < 128) sB1[tid] = b1[tid];
    if (tid >= 128 && tid < 192) sB2[tid - 128] = b2[tid - 128];

    const int node0 = blockIdx.x * 64;
    for (int i = tid; i < 64 * 64; i += 256) {
        int ln = i >> 6, f = i & 63;
        int n = node0 + ln;
        if (n < N_NODES) {
            sM[i] = g_mean1[n * 64 + f];
            sX[i] = x[n * 64 + f];
        } else { sM[i] = 0.f; sX[i] = 0.f; }
    }
    __syncthreads();

    // ---- GEMM1: 8 nodes x 4 cols (2 col-pairs) per thread, f32x2 FMA ----
    const int c4 = (tid & 31) * 4;     // 0..124 (16B aligned -> ull loads ok)
    const int ng = tid >> 5;           // 0..7 -> nodes ng*8 .. ng*8+7
    unsigned long long acc[8][2];
    #pragma unroll
    for (int i = 0; i < 8; i++) { acc[i][0] = 0ULL; acc[i][1] = 0ULL; }

    #pragma unroll 4
    for (int k = 0; k < 64; k += 4) {
        float4 mv[8], xv[8];
        #pragma unroll
        for (int i = 0; i < 8; i++) {
            int ln = ng * 8 + i;
            mv[i] = *(const float4*)&sM[ln * 64 + k];
            xv[i] = *(const float4*)&sX[ln * 64 + k];
        }
        #pragma unroll
        for (int kk = 0; kk < 4; kk++) {
            const unsigned long long wl01 = *(const unsigned long long*)&sWl[(k + kk) * 128 + c4];
            const unsigned long long wl23 = *(const unsigned long long*)&sWl[(k + kk) * 128 + c4 + 2];
            const unsigned long long wr01 = *(const unsigned long long*)&sWr[(k + kk) * 128 + c4];
            const unsigned long long wr23 = *(const unsigned long long*)&sWr[(k + kk) * 128 + c4 + 2];
            #pragma unroll
            for (int i = 0; i < 8; i++) {
                float m  = (&mv[i].x)[kk];
                float xx = (&xv[i].x)[kk];
                unsigned long long mm = pack2(m, m);
                unsigned long long xx2 = pack2(xx, xx);
                fma2(acc[i][0], wl01, mm);
                fma2(acc[i][1], wl23, mm);
                fma2(acc[i][0], wr01, xx2);
                fma2(acc[i][1], wr23, xx2);
            }
        }
    }

    float hreg[8][4];
    #pragma unroll
    for (int i = 0; i < 8; i++) {
        float2 p0 = unpack2(acc[i][0]);
        float2 p1 = unpack2(acc[i][1]);
        hreg[i][0] = fmaxf(p0.x + sB1[c4 + 0], 0.f);
        hreg[i][1] = fmaxf(p0.y + sB1[c4 + 1], 0.f);
        hreg[i][2] = fmaxf(p1.x + sB1[c4 + 2], 0.f);
        hreg[i][3] = fmaxf(p1.y + sB1[c4 + 3], 0.f);
    }

    __syncthreads();   // everyone done reading sM/sX

    #pragma unroll
    for (int i = 0; i < 8; i++) {
        int ln = ng * 8 + i;
        *(float4*)&sH[ln * 128 + c4] =
            make_float4(hreg[i][0], hreg[i][1], hreg[i][2], hreg[i][3]);
    }
    __syncthreads();

    // ---- GEMM2: hw = h@W2l, hr = h@W2r + b2 : 4 nodes x 2 col-pairs x 2 ----
    const int c4b = (tid & 15) * 4;    // 0..60
    const int ngb = tid >> 4;          // 0..15 -> nodes ngb*4 .. ngb*4+3
    unsigned long long aw2[4][2], ar2[4][2];
    #pragma unroll
    for (int i = 0; i < 4; i++) {
        aw2[i][0] = 0ULL; aw2[i][1] = 0ULL;
        ar2[i][0] = 0ULL; ar2[i][1] = 0ULL;
    }

    #pragma unroll 4
    for (int k = 0; k < 128; k += 4) {
        float4 hv[4];
        #pragma unroll
        for (int i = 0; i < 4; i++)
            hv[i] = *(const float4*)&sH[(ngb * 4 + i) * 128 + k];
        #pragma unroll
        for (int kk = 0; kk < 4; kk++) {
            const unsigned long long wl01 = *(const unsigned long long*)&sW2l[(k + kk) * 64 + c4b];
            const unsigned long long wl23 = *(const unsigned long long*)&sW2l[(k + kk) * 64 + c4b + 2];
            const unsigned long long wr01 = *(const unsigned long long*)&sW2r[(k + kk) * 64 + c4b];
            const unsigned long long wr23 = *(const unsigned long long*)&sW2r[(k + kk) * 64 + c4b + 2];
            #pragma unroll
            for (int i = 0; i < 4; i++) {
                float hh = (&hv[i].x)[kk];
                unsigned long long hh2 = pack2(hh, hh);
                fma2(aw2[i][0], wl01, hh2);
                fma2(aw2[i][1], wl23, hh2);
                fma2(ar2[i][0], wr01, hh2);
                fma2(ar2[i][1], wr23, hh2);
            }
        }
    }

    #pragma unroll
    for (int i = 0; i < 4; i++) {
        int n = node0 + ngb * 4 + i;
        if (n < N_NODES) {
            float2 w0 = unpack2(aw2[i][0]);
            float2 w1 = unpack2(aw2[i][1]);
            *(float4*)&g_hw[n * 64 + c4b] = make_float4(w0.x, w0.y, w1.x, w1.y);
            float2 r0 = unpack2(ar2[i][0]);
            float2 r1 = unpack2(ar2[i][1]);
            float4 r;
            r.x = r0.x + sB2[c4b + 0];
            r.y = r0.y + sB2[c4b + 1];
            r.z = r1.x + sB2[c4b + 2];
            r.w = r1.y + sB2[c4b + 3];
            *(float4*)&g_hr[n * 64 + c4b] = r;
        }
    }
}

// ---------------- launch ----------------------------------------------------
extern "C" void kernel_launch(void* const* d_in, const int* in_sizes, int n_in,
                              void* d_out, int out_size)
{
    const float* x   = (const float*)d_in[0];
    const void*  ei  = d_in[1];
    const float* W1l = (const float*)d_in[2];
    const float* W1r = (const float*)d_in[3];
    const float* b1  = (const float*)d_in[4];
    const float* W2l = (const float*)d_in[5];
    const float* W2r = (const float*)d_in[6];
    const float* b2  = (const float*)d_in[7];
    float* out = (float*)d_out;

    // 4 weight mats (4*8192) + biases (192) + input/h tile (8192) floats
    const int df_smem = (64 * 128 * 4 + 192 + 64 * 128) * (int)sizeof(float);   // 164608
    cudaFuncSetAttribute(dense_fused_kernel, cudaFuncAttributeMaxDynamicSharedMemorySize, df_smem);

    // --- edge-index dtype detection + CSR build ---
    detect_kernel<<<1, 32>>>(ei);
    zero_hist_kernel<<<(N_NODES + 1023) / 1024, 1024>>>();
    convert_hist_kernel<<<(N_EDGES + 255) / 256, 256>>>(ei);
    scan_blocksums_kernel<<<SCAN_NBLK, SCAN_B>>>();
    scan_blockoffsets_kernel<<<1, 32>>>();
    scan_offsets_kernel<<<SCAN_NBLK, SCAN_B>>>();
    fill_kernel<<<(N_EDGES + 255) / 256, 256>>>();

    // --- layer 1 aggregation ---
    agg1_kernel<<<(N_NODES * 16 + 255) / 256, 256>>>(x);

    // --- all dense work in one kernel (h stays in smem, f32x2 FMA) ---
    dense_fused_kernel<<<(N_NODES + 63) / 64, 256, df_smem>>>(x, W1l, W1r, b1, W2l, W2r, b2);

    // --- layer 2 aggregation + final add ---
    agg2_final_kernel<<<(N_NODES * 16 + 255) / 256, 256>>>(out);
}